// round 17
// baseline (speedup 1.0000x reference)
#include <cuda_runtime.h>

#define B  16
#define T2 2048
#define T1 512
#define F  128
#define NROWS (B * T2)
#define SPB 8           // phonemes per gather tile
#define NTILE (T1/SPB)  // 64 tiles per batch

// scratch (allocation-free rule: __device__ globals)
__device__ float  g_prop[NROWS];
__device__ float  g_act [NROWS];
__device__ float  g_imv [NROWS];
__device__ float2 g_iw  [NROWS];        // (imv, w = am*exp(-m)/Z)
__device__ float  g_dur [B * T1];       // frame-side accumulated durations
__device__ int2   g_rng [B * NTILE];    // per-tile t-support [lo, hi)

__device__ __forceinline__ float wred(float v) {
#pragma unroll
    for (int o = 16; o; o >>= 1) v += __shfl_xor_sync(0xffffffffu, v, o);
    return v;
}
__device__ __forceinline__ int wredi(int v) {
#pragma unroll
    for (int o = 16; o; o >>= 1) v += __shfl_xor_sync(0xffffffffu, v, o);
    return v;
}

// tf32 round-to-nearest (matches cuBLAS f32->tf32 input conversion)
__device__ __forceinline__ float tf32r(float x) {
    float y;
    asm("cvt.rna.tf32.f32 %0, %1;" : "=f"(y) : "f"(x));
    return y;
}

// Neumaier compensated add: (sum, comp) += x
__device__ __forceinline__ void neum_add(float& sum, float& comp, float x) {
    float t = sum + x;
    float corr = (fabsf(sum) >= fabsf(x)) ? ((sum - t) + x) : ((x - t) + sum);
    comp += corr;
    sum = t;
}

// ---------------------------------------------------------------------------
// Kernel 1: one warp per (b,t) row.  (unchanged — validated)
// ---------------------------------------------------------------------------
__global__ void k_prop_act(const float* __restrict__ mels,
                           const float* __restrict__ alpha,
                           const int*   __restrict__ mmask) {
    int warp = (blockIdx.x * blockDim.x + threadIdx.x) >> 5;
    int lane = threadIdx.x & 31;
    if (warp >= NROWS) return;
    int t = warp % T2;

    const float4* a4 = (const float4*)(alpha + (size_t)warp * T1);
    float sum0 = 0.f, c0 = 0.f;
    float sum1 = 0.f, c1 = 0.f;
    float sum2 = 0.f, c2 = 0.f;
    float sum3 = 0.f, c3 = 0.f;
#pragma unroll
    for (int i = 0; i < 4; i++) {
        int idx = lane + i * 32;
        float4 v = a4[idx];
        float s = (float)(idx * 4);
        {
            float p = v.x * s;
            float e = fmaf(v.x, s, -p);
            neum_add(sum0, c0, p); c0 += e;
        }
        {
            float s1 = s + 1.f;
            float p = v.y * s1;
            float e = fmaf(v.y, s1, -p);
            neum_add(sum1, c1, p); c1 += e;
        }
        {
            float s2 = s + 2.f;
            float p = v.z * s2;
            float e = fmaf(v.z, s2, -p);
            neum_add(sum2, c2, p); c2 += e;
        }
        {
            float s3 = s + 3.f;
            float p = v.w * s3;
            float e = fmaf(v.w, s3, -p);
            neum_add(sum3, c3, p); c3 += e;
        }
    }
    float S = sum0, C = c0;
    neum_add(S, C, sum1); C += c1;
    neum_add(S, C, sum2); C += c2;
    neum_add(S, C, sum3); C += c3;

#pragma unroll
    for (int o = 16; o; o >>= 1) {
        float oh = __shfl_xor_sync(0xffffffffu, S, o);
        float ol = __shfl_xor_sync(0xffffffffu, C, o);
        float tt = S + oh;
        float corr = (fabsf(S) >= fabsf(oh)) ? ((S - tt) + oh) : ((oh - tt) + S);
        S = tt;
        C = C + ol + corr;
    }
    float prop = S + C;

    float am = (float)mmask[warp];
    float act;
    if (t == 0) {
        act = am;
    } else {
        const float4* m1 = (const float4*)(mels + (size_t)warp * F);
        const float4* m0 = (const float4*)(mels + (size_t)(warp - 1) * F);
        float4 x = m1[lane], y = m0[lane];
        float dot = x.x * y.x + x.y * y.y + x.z * y.z + x.w * y.w;
        float n1  = x.x * x.x + x.y * x.y + x.z * x.z + x.w * x.w;
        float n0  = y.x * y.x + y.y * y.y + y.z * y.z + y.w * y.w;
        dot = wred(dot); n1 = wred(n1); n0 = wred(n0);
        float c = dot / (fmaxf(sqrtf(n0), 1e-12f) * fmaxf(sqrtf(n1), 1e-12f));
        float z = 10.f * (0.9f - c);
        act = am / (1.f + __expf(-z));
    }
    if (lane == 0) { g_prop[warp] = prop; g_act[warp] = act; }
}

// ---------------------------------------------------------------------------
// Kernel 2: per-batch scan + rescale + tile-range precompute + g_dur zero.
// ---------------------------------------------------------------------------
__global__ void k_scan(const int* __restrict__ mmask,
                       const int* __restrict__ tmask,
                       float* __restrict__ imv_out) {
    int b    = blockIdx.x;
    int tid  = threadIdx.x;       // 256
    int lane = tid & 31, wid = tid >> 5;
    const float* prop = g_prop + b * T2;
    const float* act  = g_act  + b * T2;
    const int*   mm   = mmask  + b * T2;

    __shared__ float  s_imv[T2];
    __shared__ double wsum[8];
    __shared__ int    s_msum, s_tsum;
    __shared__ float  s_scale;
    if (tid == 0) { s_msum = 0; s_tsum = 0; }
    // zero frame-side duration accumulator for this batch
    g_dur[b * T1 + tid]       = 0.f;
    g_dur[b * T1 + 256 + tid] = 0.f;
    __syncthreads();

    double vals[8];
    double run = 0.0;
    int    msum = 0;
#pragma unroll
    for (int j = 0; j < 8; j++) {
        int t = tid * 8 + j;
        float e = 0.f;
        if (t > 0) {
            e = (prop[t] - prop[t - 1]) * act[t];   // f32, as in reference
            e = fminf(fmaxf(e, 0.f), 1.f);
        }
        run += (double)e;
        vals[j] = run;
        msum += mm[t];
    }
    double tot = run;
#pragma unroll
    for (int o = 1; o < 32; o <<= 1) {
        double n = __shfl_up_sync(0xffffffffu, tot, o);
        if (lane >= o) tot += n;
    }
    if (lane == 31) wsum[wid] = tot;

    msum = wredi(msum);
    if (lane == 0) atomicAdd(&s_msum, msum);
    int tsum = tmask[b * T1 + tid] + tmask[b * T1 + 256 + tid];
    tsum = wredi(tsum);
    if (lane == 0) atomicAdd(&s_tsum, tsum);
    __syncthreads();

    if (wid == 0 && lane < 8) {
        double w = wsum[lane];
#pragma unroll
        for (int o = 1; o < 8; o <<= 1) {
            double n = __shfl_up_sync(0x000000ffu, w, o);
            if (lane >= o) w += n;
        }
        wsum[lane] = w;
    }
    __syncthreads();

    double base = (wid > 0 ? wsum[wid - 1] : 0.0) + (tot - run);
#pragma unroll
    for (int j = 0; j < 8; j++) s_imv[tid * 8 + j] = (float)(base + vals[j]);
    __syncthreads();

    if (tid == 0) {
        int vlen = s_msum;
        int li = vlen - 1; if (li < 0) li = 0;
        float lastv = fmaxf(s_imv[li] * (float)mm[li], 1e-6f);
        float tl = (float)s_tsum;
        s_scale = fmaxf(tl - 1.f, 0.f) / lastv;   // f32 divide, as in ref
    }
    __syncthreads();

    float sc = s_scale;
#pragma unroll
    for (int j = 0; j < 8; j++) {
        int t = tid * 8 + j;
        float v = s_imv[t] * sc * (float)mm[t];   // f32 mul chain, as in ref
        g_imv[b * T2 + t]   = v;
        imv_out[b * T2 + t] = v;
        s_imv[t] = v;                              // shared now holds FINAL imv
    }
    __syncthreads();

    // per-tile t-support bounds via binary search over shared final imv
    if (tid < NTILE) {
        int vlen = s_msum;
        float lob = (float)(tid * SPB) - 4.6f;
        float hib = (float)(tid * SPB + SPB - 1) + 4.6f;
        int lo = 0, hi = vlen;
        while (lo < hi) { int mid = (lo + hi) >> 1; if (s_imv[mid] < lob) lo = mid + 1; else hi = mid; }
        int a = lo;
        lo = a; hi = vlen;
        while (lo < hi) { int mid = (lo + hi) >> 1; if (s_imv[mid] <= hib) lo = mid + 1; else hi = mid; }
        g_rng[b * NTILE + tid] = make_int2(a, lo);
    }
}

// ---------------------------------------------------------------------------
// Kernel 3: per-frame softmax normalizer + frame-side duration atomics
// + zeroing of the aligned-mels output region (poisoned by harness).
// Packs (imv, w) with w = am*exp(-m)/Z  so gamma = exp(-10 d^2) * w.
// ---------------------------------------------------------------------------
__global__ void k_z(const int* __restrict__ mmask,
                    const int* __restrict__ tmask,
                    float* __restrict__ aligned) {
    int r = blockIdx.x * blockDim.x + threadIdx.x;   // 32768 threads
    // zero aligned output: 1,048,576 floats -> 8 float4 per thread
    {
        float4* al4 = (float4*)aligned;
        float4 z4 = make_float4(0.f, 0.f, 0.f, 0.f);
#pragma unroll
        for (int j = 0; j < 8; j++) al4[(size_t)r * 8 + j] = z4;
    }
    if (r >= NROWS) return;
    int b = r / T2;
    float x  = g_imv[r];
    float am = (float)mmask[r];
    const int* tm = tmask + b * T1;
    int ci = (int)floorf(x + 0.5f);
    float l[9];
    float m = -1e30f;
#pragma unroll
    for (int k = 0; k < 9; k++) {
        int s = ci + k - 4;
        float lv = -1e30f;
        if (s >= 0 && s < T1 && tm[s]) {
            float d = x - (float)s;
            lv = -10.f * d * d;
        }
        l[k] = lv;
        m = fmaxf(m, lv);
    }
    float Z = 0.f;
#pragma unroll
    for (int k = 0; k < 9; k++)
        if (l[k] > -1e29f) Z += __expf(l[k] - m);
    float zinv = (Z > 0.f) ? am / Z : 0.f;
    float w = zinv * __expf(-m);
    g_iw[r] = make_float2(x, w);

    // frame-side duration accumulation: gamma = exp(l[k]-m) * zinv
    if (zinv > 0.f) {
#pragma unroll
        for (int k = 0; k < 9; k++) {
            if (l[k] > -1e29f) {
                int s = ci + k - 4;
                atomicAdd(&g_dur[b * T1 + s], __expf(l[k] - m) * zinv);
            }
        }
    }
}

// ---------------------------------------------------------------------------
// Kernel 4: gather. Block = (tile of 8 phonemes, batch, t-half).
// No search (precomputed ranges), no duration reduce (precomputed g_dur):
// pure accumulate + atomicAdd into the zeroed aligned buffer.
// ---------------------------------------------------------------------------
__global__ void __launch_bounds__(128) k_gather(
        const float* __restrict__ mels,
        const int*   __restrict__ tmask,
        float* __restrict__ aligned,
        float* __restrict__ durs) {
    int tile = blockIdx.x;
    int b    = blockIdx.y;
    int half = blockIdx.z;
    int s0   = tile * SPB;
    int tid  = threadIdx.x;
    const float2* iw = g_iw + b * T2;

    __shared__ float s_g[SPB][132];
    __shared__ float s_tm[SPB];
    __shared__ float s_dur[SPB];
    if (tid < SPB) {
        s_tm[tid]  = (float)tmask[b * T1 + s0 + tid];
        s_dur[tid] = g_dur[b * T1 + s0 + tid];
    }
    __syncthreads();

    // half==0 writes the durations output
    if (half == 0 && tid < SPB)
        durs[b * T1 + s0 + tid] = s_dur[tid] * s_tm[tid];

    int2 rng = g_rng[b * NTILE + tile];
    int nt = rng.y - rng.x;
    if (nt <= 0) return;
    int hn   = (nt + 1) >> 1;
    int myLo = rng.x + half * hn;
    int myHi = half ? rng.y : (rng.x + hn);
    if (myLo >= myHi) return;

    float invd[SPB];
#pragma unroll
    for (int k = 0; k < SPB; k++) invd[k] = s_dur[k] + 1e-8f;

    float acc[SPB];
#pragma unroll
    for (int k = 0; k < SPB; k++) acc[k] = 0.f;

    for (int t0 = myLo; t0 < myHi; t0 += 128) {
        int t = t0 + tid;
        if (t < myHi) {
            float2 v = iw[t];
#pragma unroll
            for (int k = 0; k < SPB; k++) {
                float d = v.x - (float)(s0 + k);
                float g = __expf(-10.f * d * d) * v.y * s_tm[k];
                s_g[k][tid] = tf32r(g / invd[k]);   // normalized weight -> tf32
            }
        } else {
#pragma unroll
            for (int k = 0; k < SPB; k++) s_g[k][tid] = 0.f;
        }
        __syncthreads();

        int ntc = myHi - t0; if (ntc > 128) ntc = 128;
        const float* mp = mels + ((size_t)(b * T2 + t0)) * F + tid;
#pragma unroll 8
        for (int tt = 0; tt < ntc; tt++) {
            float mv = tf32r(mp[(size_t)tt * F]);   // mel operand -> tf32
#pragma unroll
            for (int k = 0; k < SPB; k++) acc[k] = fmaf(s_g[k][tt], mv, acc[k]);
        }
        __syncthreads();
    }

#pragma unroll
    for (int k = 0; k < SPB; k++)
        atomicAdd(&aligned[((size_t)(b * T1 + s0 + k)) * F + tid],
                  acc[k] * s_tm[k]);
}

// ---------------------------------------------------------------------------
extern "C" void kernel_launch(void* const* d_in, const int* in_sizes, int n_in,
                              void* d_out, int out_size) {
    const float* mels  = (const float*)d_in[0];
    const float* alpha = (const float*)d_in[1];
    const int*   mmask = (const int*)d_in[2];
    const int*   tmask = (const int*)d_in[3];

    float* out_al  = (float*)d_out;                       // [B,T1,F]
    float* out_dur = out_al + (size_t)B * T1 * F;         // [B,T1]
    float* out_imv = out_dur + (size_t)B * T1;            // [B,T2]

    (void)in_sizes; (void)n_in; (void)out_size;

    // 1) proposal + activity : 1 warp per (b,t)
    {
        int warps = NROWS;
        int threads = 256;
        int blocks = (warps * 32 + threads - 1) / threads;
        k_prop_act<<<blocks, threads>>>(mels, alpha, mmask);
    }
    // 2) scan + rescale + tile ranges : 1 block per batch
    k_scan<<<B, 256>>>(mmask, tmask, out_imv);
    // 3) normalizers + duration atomics + output zeroing : full-chip
    k_z<<<NROWS / 256, 256>>>(mmask, tmask, out_al);
    // 4) gather: pure accumulate, 2 t-halves per tile (2048 blocks)
    {
        dim3 grid(NTILE, B, 2);
        k_gather<<<grid, 128>>>(mels, tmask, out_al, out_dur);
    }
}